// round 2
// baseline (speedup 1.0000x reference)
#include <cuda_runtime.h>
#include <math.h>

// Dims
#define BB 16
#define NCO 64
#define NT 16
#define NHW 1024

typedef unsigned long long ull;

// ---------------- f32x2 packed helpers -------------------------------------
__device__ __forceinline__ ull fma2(ull a, ull b, ull c) {
    ull d;
    asm("fma.rn.f32x2 %0, %1, %2, %3;" : "=l"(d) : "l"(a), "l"(b), "l"(c));
    return d;
}
__device__ __forceinline__ ull pk(float lo, float hi) {
    ull d;
    asm("mov.b64 %0, {%1, %2};" : "=l"(d) : "f"(lo), "f"(hi));
    return d;
}
__device__ __forceinline__ float2 upk(ull a) {
    float lo, hi;
    asm("mov.b64 {%0, %1}, %2;" : "=f"(lo), "=f"(hi) : "l"(a));
    return make_float2(lo, hi);
}

// ---------------- persistent scratch (device globals; no allocation) -------
__device__ float g_h [BB*NCO*NHW];     // attended h (recurrent carry)   4 MB
__device__ float g_hg[BB*NCO*NHW];     // pre-attention h (gate output)  4 MB
__device__ float g_c [BB*NCO*NHW];     // cell state                     4 MB
__device__ float g_q [BB*16*NHW];      //  1 MB
__device__ float g_k [BB*16*NHW];      //  1 MB
__device__ float g_v [BB*NCO*NHW];     //  4 MB
__device__ float g_P [BB*NHW*NHW];     // attention probs               64 MB

// ---------------- init: zero h and c ---------------------------------------
__global__ void k_init()
{
    int i = blockIdx.x * 256 + threadIdx.x;
    g_h[i] = 0.f;
    g_c[i] = 0.f;
}

__device__ __forceinline__ float sigf(float x) { return 1.f / (1.f + __expf(-x)); }
__device__ __forceinline__ float tanh_fast(float x)
{
    // tanh(x) = 2/(1+exp(-2x)) - 1 ; limits handled by expf inf/0
    return __fdividef(2.f, 1.f + __expf(-2.f * x)) - 1.f;
}

// ---------------- conv 3x3 + ConvLSTM gating fused -------------------------
// grid (16 chan-groups of 4, 16 batch), 256 threads.
// Block: batch b, channels [ch0,ch0+4) x 4 gates = 16 couts, full 32x32 image.
// Thread: 4 adjacent x-positions, 16 couts -> 32 packed f32x2 accumulators.
__global__ void __launch_bounds__(256, 2) k_convgate(
    const float* __restrict__ X,   const float* __restrict__ Wc,
    const float* __restrict__ bc,
    const float* __restrict__ Wci, const float* __restrict__ Wcf,
    const float* __restrict__ Wco, int t)
{
    __shared__ float  in_s[4 * 34 * 37];   // 4 ci, 34 rows, stride 37 (20.1 KB)
    __shared__ float2 w2_s[16 * 36];       // 16 co x 36 taps, duplicated (4.6 KB)

    const int b   = blockIdx.y;
    const int ch0 = blockIdx.x * 4;
    const int tid = threadIdx.x;
    const int y   = tid >> 3;            // 0..31
    const int x4  = (tid & 7) << 2;      // 0,4,...,28

    ull acc[16][2];
    #pragma unroll
    for (int j = 0; j < 16; ++j) { acc[j][0] = 0ull; acc[j][1] = 0ull; }

    for (int ch = 0; ch < 32; ++ch) {            // 32 chunks of 4 input ch.
        // stage weights, duplicated for f32x2
        for (int i = tid; i < 576; i += 256) {
            int j = i / 36; int r = i - j * 36;
            int cog = ((j >> 2) << 6) + ch0 + (j & 3);   // gate*64 + channel
            float w = Wc[(cog * 128 + (ch * 4 + r / 9)) * 9 + (r % 9)];
            w2_s[i] = make_float2(w, w);
        }
        // stage input halo (34x34 per ci, zero-padded borders)
        for (int i = tid; i < 4 * 1156; i += 256) {
            int cc = i / 1156; int r = i - cc * 1156;
            int yy = r / 34;   int xx = r - yy * 34;
            int iy = yy - 1,   ix = xx - 1;
            int ci = ch * 4 + cc;
            const float* src = (ci < 64)
                ? (X + ((b * 64 + ci) * 16 + t) * 1024)
                : (g_h + (b * 64 + (ci - 64)) * 1024);
            float v = 0.f;
            if (iy >= 0 && iy < 32 && ix >= 0 && ix < 32) v = src[iy * 32 + ix];
            in_s[cc * 1258 + yy * 37 + xx] = v;
        }
        __syncthreads();

        const ull* wp = reinterpret_cast<const ull*>(w2_s);
        #pragma unroll
        for (int cc = 0; cc < 4; ++cc) {
            ull pv[3][5];
            #pragma unroll
            for (int dy = 0; dy < 3; ++dy) {
                float v0 = in_s[cc * 1258 + (y + dy) * 37 + x4 + 0];
                float v1 = in_s[cc * 1258 + (y + dy) * 37 + x4 + 1];
                float v2 = in_s[cc * 1258 + (y + dy) * 37 + x4 + 2];
                float v3 = in_s[cc * 1258 + (y + dy) * 37 + x4 + 3];
                float v4 = in_s[cc * 1258 + (y + dy) * 37 + x4 + 4];
                float v5 = in_s[cc * 1258 + (y + dy) * 37 + x4 + 5];
                pv[dy][0] = pk(v0, v1); pv[dy][1] = pk(v1, v2);
                pv[dy][2] = pk(v2, v3); pv[dy][3] = pk(v3, v4);
                pv[dy][4] = pk(v4, v5);
            }
            #pragma unroll
            for (int j = 0; j < 16; ++j) {
                const ull* w = wp + j * 36 + cc * 9;
                #pragma unroll
                for (int dy = 0; dy < 3; ++dy) {
                    #pragma unroll
                    for (int dx = 0; dx < 3; ++dx) {
                        ull wk = w[dy * 3 + dx];
                        acc[j][0] = fma2(pv[dy][dx],     wk, acc[j][0]);
                        acc[j][1] = fma2(pv[dy][dx + 2], wk, acc[j][1]);
                    }
                }
            }
        }
        __syncthreads();
    }

    // ---- fused gating epilogue ----
    #pragma unroll
    for (int cl = 0; cl < 4; ++cl) {
        int ch = ch0 + cl;
        float2 iA = upk(acc[0 + cl][0]),  iB = upk(acc[0 + cl][1]);
        float2 fA = upk(acc[4 + cl][0]),  fB = upk(acc[4 + cl][1]);
        float2 gA = upk(acc[8 + cl][0]),  gB = upk(acc[8 + cl][1]);
        float2 oA = upk(acc[12 + cl][0]), oB = upk(acc[12 + cl][1]);
        float iv[4] = {iA.x, iA.y, iB.x, iB.y};
        float fv[4] = {fA.x, fA.y, fB.x, fB.y};
        float gv[4] = {gA.x, gA.y, gB.x, gB.y};
        float ov[4] = {oA.x, oA.y, oB.x, oB.y};
        float bi = bc[ch], bf = bc[64 + ch], bg = bc[128 + ch], bo = bc[192 + ch];
        #pragma unroll
        for (int p = 0; p < 4; ++p) {
            int pos = y * 32 + x4 + p;
            int idx = (b * 64 + ch) * 1024 + pos;
            int wpp = ch * 1024 + pos;
            float cp = g_c[idx];
            float ii = sigf(iv[p] + bi + Wci[wpp] * cp);
            float ff = sigf(fv[p] + bf + Wcf[wpp] * cp);
            float nc = ff * cp + ii * tanh_fast(gv[p] + bg);
            float oo = sigf(ov[p] + bo + Wco[wpp] * nc);
            g_c[idx]  = nc;
            g_hg[idx] = oo * tanh_fast(nc);
        }
    }
}

// ---------------- q,k,v 1x1 convs: 96 output ch from 64 --------------------
// grid (4 pos-tiles, 12 oc-groups of 8, 16 batch), 256 threads (1 pos each).
__global__ void k_qkv(const float* __restrict__ qw, const float* __restrict__ qb,
                      const float* __restrict__ kw, const float* __restrict__ kb,
                      const float* __restrict__ vw, const float* __restrict__ vb)
{
    __shared__ float h_s[32 * 256];   // 32 KB, half the channels at a time
    __shared__ float wt_s[64 * 8];    // transposed: [c][j], 2 KB

    const int p0  = blockIdx.x * 256;
    const int oc0 = blockIdx.y * 8;
    const int b   = blockIdx.z;
    const int tid = threadIdx.x;

    for (int i = tid; i < 512; i += 256) {
        int j = i >> 6; int c = i & 63; int oc = oc0 + j;
        float w = (oc < 16) ? qw[oc * 64 + c]
                : (oc < 32) ? kw[(oc - 16) * 64 + c]
                            : vw[(oc - 32) * 64 + c];
        wt_s[c * 8 + j] = w;
    }

    ull acc[4];
    #pragma unroll
    for (int jj = 0; jj < 4; ++jj) {
        int oc_a = oc0 + 2 * jj, oc_b = oc_a + 1;
        float ba = (oc_a < 16) ? qb[oc_a] : (oc_a < 32) ? kb[oc_a - 16] : vb[oc_a - 32];
        float bb = (oc_b < 16) ? qb[oc_b] : (oc_b < 32) ? kb[oc_b - 16] : vb[oc_b - 32];
        acc[jj] = pk(ba, bb);
    }

    const ull* wt2 = reinterpret_cast<const ull*>(wt_s);
    for (int chh = 0; chh < 2; ++chh) {
        __syncthreads();
        for (int i = tid; i < 8192; i += 256) {
            int c = i >> 8; int j = i & 255;
            h_s[i] = g_hg[(b * 64 + chh * 32 + c) * 1024 + p0 + j];
        }
        __syncthreads();
        #pragma unroll 8
        for (int c = 0; c < 32; ++c) {
            float hv = h_s[c * 256 + tid];
            ull hv2 = pk(hv, hv);
            int cg = chh * 32 + c;
            #pragma unroll
            for (int jj = 0; jj < 4; ++jj)
                acc[jj] = fma2(wt2[cg * 4 + jj], hv2, acc[jj]);
        }
    }

    int pos = p0 + tid;
    #pragma unroll
    for (int jj = 0; jj < 4; ++jj) {
        float2 u = upk(acc[jj]);
        float vals[2] = {u.x, u.y};
        #pragma unroll
        for (int hh = 0; hh < 2; ++hh) {
            int oc = oc0 + 2 * jj + hh;
            float vvv = vals[hh];
            if (oc < 16)      g_q[(b * 16 + oc) * 1024 + pos]        = vvv;
            else if (oc < 32) g_k[(b * 16 + (oc - 16)) * 1024 + pos] = vvv;
            else              g_v[(b * 64 + (oc - 32)) * 1024 + pos] = vvv;
        }
    }
}

// ---------------- scores + softmax fused: P[b][n][m] ------------------------
// grid (64 row-groups, 16 batch), 256 threads. Warp = 2 rows, packed in f32x2.
__global__ void __launch_bounds__(256) k_scores()
{
    __shared__ float2 k2_s[16 * 256];   // 32 KB, quarter of m-range, duplicated
    const int b    = blockIdx.y;
    const int r0   = blockIdx.x * 16 + ((threadIdx.x >> 5) << 1);
    const int lane = threadIdx.x & 31;

    ull q01[16];
    #pragma unroll
    for (int c = 0; c < 16; ++c)   // r0 even -> 8B-aligned pair (row r0, r0+1)
        q01[c] = *reinterpret_cast<const ull*>(&g_q[(b * 16 + c) * 1024 + r0]);

    ull s01[32];
    const ull* k2 = reinterpret_cast<const ull*>(k2_s);
    for (int chh = 0; chh < 4; ++chh) {
        __syncthreads();
        for (int i = threadIdx.x; i < 4096; i += 256) {
            int c = i >> 8; int mm = i & 255;
            float kv = g_k[(b * 16 + c) * 1024 + chh * 256 + mm];
            k2_s[i] = make_float2(kv, kv);
        }
        __syncthreads();
        #pragma unroll
        for (int jj = 0; jj < 8; ++jj) {
            int j  = chh * 8 + jj;
            int mm = jj * 32 + lane;
            ull a = 0ull;
            #pragma unroll
            for (int c = 0; c < 16; ++c)
                a = fma2(q01[c], k2[c * 256 + mm], a);
            s01[j] = a;
        }
    }

    float s0[32], s1[32];
    #pragma unroll
    for (int j = 0; j < 32; ++j) { float2 u = upk(s01[j]); s0[j] = u.x; s1[j] = u.y; }

    float m0 = -1e30f, m1 = -1e30f;
    #pragma unroll
    for (int j = 0; j < 32; ++j) { m0 = fmaxf(m0, s0[j]); m1 = fmaxf(m1, s1[j]); }
    #pragma unroll
    for (int o = 16; o > 0; o >>= 1) {
        m0 = fmaxf(m0, __shfl_xor_sync(0xffffffffu, m0, o));
        m1 = fmaxf(m1, __shfl_xor_sync(0xffffffffu, m1, o));
    }
    float sum0 = 0.f, sum1 = 0.f;
    #pragma unroll
    for (int j = 0; j < 32; ++j) {
        s0[j] = __expf(s0[j] - m0); sum0 += s0[j];
        s1[j] = __expf(s1[j] - m1); sum1 += s1[j];
    }
    #pragma unroll
    for (int o = 16; o > 0; o >>= 1) {
        sum0 += __shfl_xor_sync(0xffffffffu, sum0, o);
        sum1 += __shfl_xor_sync(0xffffffffu, sum1, o);
    }
    float inv0 = 1.f / sum0, inv1 = 1.f / sum1;

    float* P0 = g_P + b * 1048576 + r0 * 1024;
    #pragma unroll
    for (int j = 0; j < 32; ++j) {
        P0[j * 32 + lane]        = s0[j] * inv0;
        P0[1024 + j * 32 + lane] = s1[j] * inv1;
    }
}

// ---------------- z = P @ v^T, fused with z_w 1x1 + output write -----------
// grid (8 n-tiles of 128, 16 batch), 256 threads. Warp = 8 channels,
// lane = 4 n-columns (l, l+32, l+64, l+96), packed as (l,l+32),(l+64,l+96).
__global__ void __launch_bounds__(256) k_zout(
    const float* __restrict__ zw, const float* __restrict__ zb,
    float* __restrict__ out, int t)
{
    __shared__ float smem[12288];          // 48 KB, phase-unioned
    float*  P_s  = smem;                   // phase 1: 128 x 33   (16896 B)
    float2* v_s2 = (float2*)(smem + 4224); // phase 1: 64 x 32 dup (16384 B)
    float*  z_s  = smem;                   // phase 2: 64 x 128   (32768 B)
    float*  zw_s = smem + 8192;            // phase 2: 64 x 64    (16384 B)

    const int b   = blockIdx.y;
    const int n0  = blockIdx.x * 128;
    const int tid = threadIdx.x;
    const int w   = tid >> 5;
    const int l   = tid & 31;

    ull acc[8][2];
    #pragma unroll
    for (int ci = 0; ci < 8; ++ci) { acc[ci][0] = 0ull; acc[ci][1] = 0ull; }

    const ull* v2 = reinterpret_cast<const ull*>(v_s2);
    for (int m0 = 0; m0 < 1024; m0 += 32) {
        for (int i = tid; i < 4096; i += 256) {
            int nl = i >> 5; int kk = i & 31;
            P_s[nl * 33 + kk] = g_P[b * 1048576 + (n0 + nl) * 1024 + m0 + kk];
        }
        for (int i = tid; i < 2048; i += 256) {
            int c = i >> 5; int kk = i & 31;
            float vv = g_v[(b * 64 + c) * 1024 + m0 + kk];
            v_s2[i] = make_float2(vv, vv);
        }
        __syncthreads();
        #pragma unroll 4
        for (int kk = 0; kk < 32; ++kk) {
            float p0v = P_s[(l     ) * 33 + kk];
            float p1v = P_s[(l + 32) * 33 + kk];
            float p2v = P_s[(l + 64) * 33 + kk];
            float p3v = P_s[(l + 96) * 33 + kk];
            ull pA = pk(p0v, p1v), pB = pk(p2v, p3v);
            #pragma unroll
            for (int ci = 0; ci < 8; ++ci) {
                ull vv2 = v2[(w * 8 + ci) * 32 + kk];
                acc[ci][0] = fma2(pA, vv2, acc[ci][0]);
                acc[ci][1] = fma2(pB, vv2, acc[ci][1]);
            }
        }
        __syncthreads();
    }

    // stash z tile, stage z_w
    #pragma unroll
    for (int ci = 0; ci < 8; ++ci) {
        float2 uA = upk(acc[ci][0]), uB = upk(acc[ci][1]);
        z_s[(w * 8 + ci) * 128 + l     ] = uA.x;
        z_s[(w * 8 + ci) * 128 + l + 32] = uA.y;
        z_s[(w * 8 + ci) * 128 + l + 64] = uB.x;
        z_s[(w * 8 + ci) * 128 + l + 96] = uB.y;
    }
    for (int i = tid; i < 4096; i += 256) zw_s[i] = zw[i];
    __syncthreads();

    // attended = z_w @ z + z_b
    float acc2[8][4];
    #pragma unroll
    for (int ci = 0; ci < 8; ++ci) {
        float bv = zb[w * 8 + ci];
        #pragma unroll
        for (int i = 0; i < 4; ++i) acc2[ci][i] = bv;
    }
    #pragma unroll 8
    for (int c = 0; c < 64; ++c) {
        float pv[4];
        #pragma unroll
        for (int i = 0; i < 4; ++i) pv[i] = z_s[c * 128 + l + 32 * i];
        #pragma unroll
        for (int ci = 0; ci < 8; ++ci) {
            float wv = zw_s[(w * 8 + ci) * 64 + c];
            #pragma unroll
            for (int i = 0; i < 4; ++i) acc2[ci][i] += wv * pv[i];
        }
    }

    #pragma unroll
    for (int ci = 0; ci < 8; ++ci) {
        int oc = w * 8 + ci;
        #pragma unroll
        for (int i = 0; i < 4; ++i) {
            int n = n0 + l + 32 * i;
            float val = acc2[ci][i];
            g_h[(b * 64 + oc) * 1024 + n] = val;                  // recurrent carry
            out[((b * 64 + oc) * 16 + t) * 1024 + n] = val;       // (B,C,T,H,W)
        }
    }
}

// ---------------- orchestration --------------------------------------------
extern "C" void kernel_launch(void* const* d_in, const int* in_sizes, int n_in,
                              void* d_out, int out_size)
{
    (void)in_sizes; (void)n_in; (void)out_size;
    const float* X   = (const float*)d_in[0];
    const float* Wc  = (const float*)d_in[1];
    const float* bcc = (const float*)d_in[2];
    const float* Wci = (const float*)d_in[3];
    const float* Wcf = (const float*)d_in[4];
    const float* Wco = (const float*)d_in[5];
    const float* qw  = (const float*)d_in[6];
    const float* qb  = (const float*)d_in[7];
    const float* kw  = (const float*)d_in[8];
    const float* kb  = (const float*)d_in[9];
    const float* vw  = (const float*)d_in[10];
    const float* vb  = (const float*)d_in[11];
    const float* zw  = (const float*)d_in[12];
    const float* zb  = (const float*)d_in[13];
    float* out = (float*)d_out;

    k_init<<<4096, 256>>>();
    for (int t = 0; t < NT; ++t) {
        k_convgate<<<dim3(16, 16),    256>>>(X, Wc, bcc, Wci, Wcf, Wco, t);
        k_qkv     <<<dim3(4, 12, 16), 256>>>(qw, qb, kw, kb, vw, vb);
        k_scores  <<<dim3(64, 16),    256>>>();
        k_zout    <<<dim3(8, 16),     256>>>(zw, zb, out, t);
    }
}

// round 3
// speedup vs baseline: 1.2164x; 1.2164x over previous
#include <cuda_runtime.h>
#include <math.h>

// Dims
#define BB 16
#define NCO 64
#define NT 16
#define NHW 1024

// ---------------- persistent scratch (device globals; no allocation) -------
__device__ float g_h [BB*NCO*NHW];     // attended h (recurrent carry)   4 MB
__device__ float g_hg[BB*NCO*NHW];     // pre-attention h (gate output)  4 MB
__device__ float g_c [BB*NCO*NHW];     // cell state                     4 MB
__device__ float g_q [BB*16*NHW];      //  1 MB
__device__ float g_k [BB*16*NHW];      //  1 MB
__device__ float g_v [BB*NCO*NHW];     //  4 MB

// ---------------- init: zero h and c ---------------------------------------
__global__ void k_init()
{
    int i = blockIdx.x * 256 + threadIdx.x;
    g_h[i] = 0.f;
    g_c[i] = 0.f;
}

__device__ __forceinline__ float sigf(float x) { return 1.f / (1.f + __expf(-x)); }
__device__ __forceinline__ float tanh_fast(float x)
{
    return __fdividef(2.f, 1.f + __expf(-2.f * x)) - 1.f;
}

// ---------------- conv 3x3 + ConvLSTM gating fused -------------------------
// grid (16 chan-groups of 4, 16 batch), 256 threads.
// Block: batch b, couts = {gate*64 + ch0 + cl : gate 0..3, cl 0..3}, full image.
// Thread: 4 adjacent x-positions, 16 couts -> 64 scalar accumulators.
__global__ void __launch_bounds__(256, 2) k_convgate(
    const float* __restrict__ X,   const float* __restrict__ Wc,
    const float* __restrict__ bc,
    const float* __restrict__ Wci, const float* __restrict__ Wcf,
    const float* __restrict__ Wco, int t)
{
    __shared__ float in_s[4 * 34 * 37];   // 4 ci, 34 rows, stride 37 (20.1 KB)
    __shared__ float w_s[16 * 36];        // 16 co x 4 ci x 9           (2.3 KB)

    const int b   = blockIdx.y;
    const int ch0 = blockIdx.x * 4;
    const int tid = threadIdx.x;
    const int y   = tid >> 3;            // 0..31
    const int x4  = (tid & 7) << 2;      // 0,4,...,28

    float acc[16][4];
    #pragma unroll
    for (int j = 0; j < 16; ++j)
        #pragma unroll
        for (int p = 0; p < 4; ++p) acc[j][p] = 0.f;

    for (int ch = 0; ch < 32; ++ch) {            // 32 chunks of 4 input ch.
        // stage weights (j = gate*4 + cl  ->  cout = gate*64 + ch0 + cl)
        for (int i = tid; i < 576; i += 256) {
            int j = i / 36; int r = i - j * 36;
            int cog = ((j >> 2) << 6) + ch0 + (j & 3);
            w_s[i] = Wc[(cog * 128 + (ch * 4 + r / 9)) * 9 + (r % 9)];
        }
        // stage input halo (34x34 per ci, zero-padded borders)
        for (int i = tid; i < 4 * 1156; i += 256) {
            int cc = i / 1156; int r = i - cc * 1156;
            int yy = r / 34;   int xx = r - yy * 34;
            int iy = yy - 1,   ix = xx - 1;
            int ci = ch * 4 + cc;
            const float* src = (ci < 64)
                ? (X + ((b * 64 + ci) * 16 + t) * 1024)
                : (g_h + (b * 64 + (ci - 64)) * 1024);
            float v = 0.f;
            if (iy >= 0 && iy < 32 && ix >= 0 && ix < 32) v = src[iy * 32 + ix];
            in_s[cc * 1258 + yy * 37 + xx] = v;
        }
        __syncthreads();

        #pragma unroll
        for (int cc = 0; cc < 4; ++cc) {
            float v[3][6];
            #pragma unroll
            for (int dy = 0; dy < 3; ++dy)
                #pragma unroll
                for (int dx = 0; dx < 6; ++dx)
                    v[dy][dx] = in_s[cc * 1258 + (y + dy) * 37 + (x4 + dx)];
            #pragma unroll
            for (int j = 0; j < 16; ++j) {
                const float* wp = &w_s[j * 36 + cc * 9];
                float w0 = wp[0], w1 = wp[1], w2 = wp[2];
                float w3 = wp[3], w4 = wp[4], w5 = wp[5];
                float w6 = wp[6], w7 = wp[7], w8 = wp[8];
                #pragma unroll
                for (int p = 0; p < 4; ++p) {
                    acc[j][p] += w0 * v[0][p] + w1 * v[0][p + 1] + w2 * v[0][p + 2]
                               + w3 * v[1][p] + w4 * v[1][p + 1] + w5 * v[1][p + 2]
                               + w6 * v[2][p] + w7 * v[2][p + 1] + w8 * v[2][p + 2];
                }
            }
        }
        __syncthreads();
    }

    // ---- fused gating epilogue ----
    #pragma unroll
    for (int cl = 0; cl < 4; ++cl) {
        int ch = ch0 + cl;
        float bi = bc[ch], bf = bc[64 + ch], bg = bc[128 + ch], bo = bc[192 + ch];
        #pragma unroll
        for (int p = 0; p < 4; ++p) {
            int pos = y * 32 + x4 + p;
            int idx = (b * 64 + ch) * 1024 + pos;
            int wpp = ch * 1024 + pos;
            float cp = g_c[idx];
            float ii = sigf(acc[cl][p]      + bi + Wci[wpp] * cp);
            float ff = sigf(acc[4 + cl][p]  + bf + Wcf[wpp] * cp);
            float nc = ff * cp + ii * tanh_fast(acc[8 + cl][p] + bg);
            float oo = sigf(acc[12 + cl][p] + bo + Wco[wpp] * nc);
            g_c[idx]  = nc;
            g_hg[idx] = oo * tanh_fast(nc);
        }
    }
}

// ---------------- q,k,v 1x1 convs: 96 output ch from 64 --------------------
// grid (4 pos-tiles, 12 oc-groups of 8, 16 batch), 256 threads (1 pos each).
__global__ void k_qkv(const float* __restrict__ qw, const float* __restrict__ qb,
                      const float* __restrict__ kw, const float* __restrict__ kb,
                      const float* __restrict__ vw, const float* __restrict__ vb)
{
    __shared__ float h_s[32 * 256];   // 32 KB, half the channels at a time
    __shared__ float w_s[8 * 64];     // 2 KB

    const int p0  = blockIdx.x * 256;
    const int oc0 = blockIdx.y * 8;
    const int b   = blockIdx.z;
    const int tid = threadIdx.x;

    for (int i = tid; i < 512; i += 256) {
        int j = i >> 6; int c = i & 63; int oc = oc0 + j;
        w_s[i] = (oc < 16) ? qw[oc * 64 + c]
               : (oc < 32) ? kw[(oc - 16) * 64 + c]
                           : vw[(oc - 32) * 64 + c];
    }

    float acc[8];
    #pragma unroll
    for (int j = 0; j < 8; ++j) {
        int oc = oc0 + j;
        acc[j] = (oc < 16) ? qb[oc] : (oc < 32) ? kb[oc - 16] : vb[oc - 32];
    }

    for (int chh = 0; chh < 2; ++chh) {
        __syncthreads();
        for (int i = tid; i < 8192; i += 256) {
            int c = i >> 8; int j = i & 255;
            h_s[i] = g_hg[(b * 64 + chh * 32 + c) * 1024 + p0 + j];
        }
        __syncthreads();
        #pragma unroll 8
        for (int c = 0; c < 32; ++c) {
            float hv = h_s[c * 256 + tid];
            #pragma unroll
            for (int j = 0; j < 8; ++j)
                acc[j] += w_s[j * 64 + chh * 32 + c] * hv;
        }
    }

    int pos = p0 + tid;
    #pragma unroll
    for (int j = 0; j < 8; ++j) {
        int oc = oc0 + j;
        if (oc < 16)      g_q[(b * 16 + oc) * 1024 + pos]        = acc[j];
        else if (oc < 32) g_k[(b * 16 + (oc - 16)) * 1024 + pos] = acc[j];
        else              g_v[(b * 64 + (oc - 32)) * 1024 + pos] = acc[j];
    }
}

// ---------------- fused attention: scores+softmax+P@v^T+z_w+write ----------
// grid (64 row-groups of 16, 16 batch), 256 threads = 8 warps.
// Warp = 2 rows; P for those rows stays register-resident (32 regs/row,
// lane l holds m = chunk*256 + jj*32 + l). g_P eliminated entirely.
__global__ void __launch_bounds__(256, 2) k_attn(
    const float* __restrict__ zw, const float* __restrict__ zb,
    float* __restrict__ out, int t)
{
    __shared__ float u_s[8192];       // 32 KB union: k(16x256) / v(8x1024) / zw(64x64)
    __shared__ float z_s[64 * 16];    // 4 KB: z[ch][row]

    const int b    = blockIdx.y;
    const int n0   = blockIdx.x * 16;
    const int tid  = threadIdx.x;
    const int w    = tid >> 5;
    const int lane = tid & 31;
    const int rl   = w * 2;           // local row of this warp's first row
    const int r0   = n0 + rl;

    // ---- phase A: scores s[32] per row (q . k) ----
    float q0[16], q1[16];
    #pragma unroll
    for (int c = 0; c < 16; ++c) {
        q0[c] = g_q[(b * 16 + c) * 1024 + r0];
        q1[c] = g_q[(b * 16 + c) * 1024 + r0 + 1];
    }

    float s0[32], s1[32];
    for (int chh = 0; chh < 4; ++chh) {
        __syncthreads();
        for (int i = tid; i < 4096; i += 256) {
            int c = i >> 8; int mm = i & 255;
            u_s[i] = g_k[(b * 16 + c) * 1024 + chh * 256 + mm];
        }
        __syncthreads();
        #pragma unroll
        for (int jj = 0; jj < 8; ++jj) {
            int j  = chh * 8 + jj;
            int mm = jj * 32 + lane;
            float a = 0.f, bb2 = 0.f;
            #pragma unroll
            for (int c = 0; c < 16; ++c) {
                float kv = u_s[c * 256 + mm];
                a   += q0[c] * kv;
                bb2 += q1[c] * kv;
            }
            s0[j] = a; s1[j] = bb2;
        }
    }

    // ---- phase B: softmax over m (registers + warp butterflies) ----
    float m0 = -1e30f, m1 = -1e30f;
    #pragma unroll
    for (int j = 0; j < 32; ++j) { m0 = fmaxf(m0, s0[j]); m1 = fmaxf(m1, s1[j]); }
    #pragma unroll
    for (int o = 16; o > 0; o >>= 1) {
        m0 = fmaxf(m0, __shfl_xor_sync(0xffffffffu, m0, o));
        m1 = fmaxf(m1, __shfl_xor_sync(0xffffffffu, m1, o));
    }
    float sum0 = 0.f, sum1 = 0.f;
    #pragma unroll
    for (int j = 0; j < 32; ++j) {
        s0[j] = __expf(s0[j] - m0); sum0 += s0[j];
        s1[j] = __expf(s1[j] - m1); sum1 += s1[j];
    }
    #pragma unroll
    for (int o = 16; o > 0; o >>= 1) {
        sum0 += __shfl_xor_sync(0xffffffffu, sum0, o);
        sum1 += __shfl_xor_sync(0xffffffffu, sum1, o);
    }
    float inv0 = 1.f / sum0, inv1 = 1.f / sum1;
    #pragma unroll
    for (int j = 0; j < 32; ++j) { s0[j] *= inv0; s1[j] *= inv1; }

    // ---- phase C: z[ch][row] = sum_m P[row][m] * v[ch][m], 8-ch chunks ----
    for (int cc8 = 0; cc8 < 64; cc8 += 8) {
        __syncthreads();
        for (int i = tid; i < 8192; i += 256) {
            int c = i >> 10; int mm = i & 1023;
            u_s[i] = g_v[(b * 64 + cc8 + c) * 1024 + mm];
        }
        __syncthreads();

        float a0[8], a1[8];
        #pragma unroll
        for (int c = 0; c < 8; ++c) { a0[c] = 0.f; a1[c] = 0.f; }
        #pragma unroll
        for (int j = 0; j < 32; ++j) {
            int moff = ((j >> 3) << 8) + ((j & 7) << 5) + lane;
            float p0v = s0[j], p1v = s1[j];
            #pragma unroll
            for (int c = 0; c < 8; ++c) {
                float vv = u_s[c * 1024 + moff];
                a0[c] += p0v * vv;
                a1[c] += p1v * vv;
            }
        }
        // cross-lane m-reduction (after butterfly, every lane has the sum)
        #pragma unroll
        for (int c = 0; c < 8; ++c) {
            #pragma unroll
            for (int o = 16; o > 0; o >>= 1) {
                a0[c] += __shfl_xor_sync(0xffffffffu, a0[c], o);
                a1[c] += __shfl_xor_sync(0xffffffffu, a1[c], o);
            }
        }
        // lanes 0..7 write row rl, lanes 8..15 write row rl+1
        float out_v = 0.f;
        #pragma unroll
        for (int c = 0; c < 8; ++c) {
            if (lane == c)     out_v = a0[c];
            if (lane == c + 8) out_v = a1[c];
        }
        if (lane < 16) {
            int row = rl + (lane >> 3);
            int chn = cc8 + (lane & 7);
            z_s[chn * 16 + row] = out_v;
        }
    }

    // ---- phase D: attended = z_w @ z + z_b; write out + g_h ----
    __syncthreads();
    for (int i = tid; i < 4096; i += 256) u_s[i] = zw[i];
    __syncthreads();

    const int oc = tid >> 2;
    const int rg = (tid & 3) << 2;
    float a4[4];
    float bv = zb[oc];
    #pragma unroll
    for (int i = 0; i < 4; ++i) a4[i] = bv;
    #pragma unroll 8
    for (int c = 0; c < 64; ++c) {
        float wv = u_s[oc * 64 + c];
        float4 zv = *reinterpret_cast<const float4*>(&z_s[c * 16 + rg]);
        a4[0] += wv * zv.x; a4[1] += wv * zv.y;
        a4[2] += wv * zv.z; a4[3] += wv * zv.w;
    }
    #pragma unroll
    for (int i = 0; i < 4; ++i) {
        int n = n0 + rg + i;
        g_h[(b * 64 + oc) * 1024 + n] = a4[i];
        out[((b * 64 + oc) * 16 + t) * 1024 + n] = a4[i];
    }
}

// ---------------- orchestration --------------------------------------------
extern "C" void kernel_launch(void* const* d_in, const int* in_sizes, int n_in,
                              void* d_out, int out_size)
{
    (void)in_sizes; (void)n_in; (void)out_size;
    const float* X   = (const float*)d_in[0];
    const float* Wc  = (const float*)d_in[1];
    const float* bcc = (const float*)d_in[2];
    const float* Wci = (const float*)d_in[3];
    const float* Wcf = (const float*)d_in[4];
    const float* Wco = (const float*)d_in[5];
    const float* qw  = (const float*)d_in[6];
    const float* qb  = (const float*)d_in[7];
    const float* kw  = (const float*)d_in[8];
    const float* kb  = (const float*)d_in[9];
    const float* vw  = (const float*)d_in[10];
    const float* vb  = (const float*)d_in[11];
    const float* zw  = (const float*)d_in[12];
    const float* zb  = (const float*)d_in[13];
    float* out = (float*)d_out;

    k_init<<<4096, 256>>>();
    for (int t = 0; t < NT; ++t) {
        k_convgate<<<dim3(16, 16),    256>>>(X, Wc, bcc, Wci, Wcf, Wco, t);
        k_qkv     <<<dim3(4, 12, 16), 256>>>(qw, qb, kw, kb, vw, vb);
        k_attn    <<<dim3(64, 16),    256>>>(zw, zb, out, t);
    }
}